// round 13
// baseline (speedup 1.0000x reference)
#include <cuda_runtime.h>
#include <cuda_fp16.h>
#include <cstdint>

#define T_TOK   8192
#define H_DIM   1024
#define I_DIM   512
#define E_EXP   8
#define EZ_EXP  12
#define SCALE_F 2.5f

typedef unsigned int u32;
typedef unsigned long long u64;

// ---------------- scratch (device globals; no allocation) ----------------
__device__ int    g_top_idx[T_TOK * 2];
__device__ float  g_top_w[T_TOK * 2];
__device__ float  g_zero_scale[T_TOK];
__device__ int    g_counts[E_EXP];
__device__ int    g_blk[E_EXP][16];
__device__ int    g_rows[E_EXP * T_TOK];
__device__ __half g_xh[(size_t)T_TOK * H_DIM];
__device__ __half g_w13h[(size_t)E_EXP * 2 * I_DIM * H_DIM];
__device__ __half g_w2h[(size_t)E_EXP * H_DIM * I_DIM];
__device__ __half g_acth[(size_t)T_TOK * 2 * I_DIM];
__device__ __half g_yh[(size_t)T_TOK * 2 * H_DIM];

// ---------------- helpers ----------------
__device__ __forceinline__ u32 smem_u32(const void* p) {
    u32 a;
    asm("{ .reg .u64 t; cvta.to.shared.u64 t, %1; cvt.u32.u64 %0, t; }" : "=r"(a) : "l"(p));
    return a;
}

#define CPA16(dst, src) \
    asm volatile("{.reg .u64 g; cvta.to.global.u64 g, %1; cp.async.cg.shared.global [%0], [g], 16;}\n" \
                 :: "r"((u32)(dst)), "l"(src) : "memory")
#define CPCOMMIT() asm volatile("cp.async.commit_group;" ::: "memory")
#define CPWAIT0()  asm volatile("cp.async.wait_group 0;" ::: "memory")

__device__ __forceinline__ void ldsm4(u32& r0, u32& r1, u32& r2, u32& r3, u32 addr) {
    asm volatile("ldmatrix.sync.aligned.m8n8.x4.shared.b16 {%0,%1,%2,%3}, [%4];"
                 : "=r"(r0), "=r"(r1), "=r"(r2), "=r"(r3) : "r"(addr));
}

__device__ __forceinline__ void mma_f16(float* d, const u32* a, u32 b0, u32 b1) {
    asm volatile("mma.sync.aligned.m16n8k16.row.col.f32.f16.f16.f32 "
        "{%0,%1,%2,%3}, {%4,%5,%6,%7}, {%8,%9}, {%0,%1,%2,%3};"
        : "+f"(d[0]), "+f"(d[1]), "+f"(d[2]), "+f"(d[3])
        : "r"(a[0]), "r"(a[1]), "r"(a[2]), "r"(a[3]), "r"(b0), "r"(b1));
}

// ============================================================================
// weight conversion (one-time) + zero g_blk for the router's atomic counting
// ============================================================================
#define W13_ELEMS ((size_t)E_EXP * 2 * I_DIM * H_DIM)
__global__ void __launch_bounds__(256) cvt_w_kernel(
    const float* __restrict__ w13, const float* __restrict__ w2)
{
    if (blockIdx.x == 0 && threadIdx.x < E_EXP * 16)
        ((int*)g_blk)[threadIdx.x] = 0;

    const size_t gid = (size_t)blockIdx.x * 256 + threadIdx.x;
    const float* src; __half* dst; size_t off;
    if (gid < W13_ELEMS / 4) { src = w13; dst = g_w13h; off = gid * 4; }
    else { src = w2; dst = g_w2h; off = (gid - W13_ELEMS / 4) * 4; }
    const float4 v = *(const float4*)(src + off);
    *(__half2*)(dst + off)     = __halves2half2(__float2half_rn(v.x), __float2half_rn(v.y));
    *(__half2*)(dst + off + 2) = __halves2half2(__float2half_rn(v.z), __float2half_rn(v.w));
}

// ============================================================================
// router + fused x->fp16 conversion + fused per-chunk expert counting (proven)
// ============================================================================
__global__ void __launch_bounds__(256) router_kernel(
    const float* __restrict__ x, const float* __restrict__ rw, const float* __restrict__ bias)
{
    __shared__ float srw[EZ_EXP * H_DIM];
    const int tid = threadIdx.x;
    for (int i = tid; i < EZ_EXP * H_DIM; i += 256) srw[i] = rw[i];
    __syncthreads();

    const int warp = tid >> 5, lane = tid & 31;
    const int t0 = blockIdx.x * 16 + warp * 2;
    const int chunk = blockIdx.x >> 5;
    const float* xr0 = x + (size_t)t0 * H_DIM;
    const float* xr1 = x + (size_t)(t0 + 1) * H_DIM;

    float xv0[32], xv1[32];
#pragma unroll
    for (int j = 0; j < 32; j++) { xv0[j] = xr0[lane + 32 * j]; xv1[j] = xr1[lane + 32 * j]; }

    __half* xh0 = g_xh + (size_t)t0 * H_DIM;
    __half* xh1 = g_xh + (size_t)(t0 + 1) * H_DIM;
#pragma unroll
    for (int j = 0; j < 32; j++) {
        xh0[lane + 32 * j] = __float2half_rn(xv0[j]);
        xh1[lane + 32 * j] = __float2half_rn(xv1[j]);
    }

    float lg[2][EZ_EXP];
#pragma unroll
    for (int e = 0; e < EZ_EXP; e++) {
        const float* wr = srw + e * H_DIM;
        float a0 = 0.f, a1 = 0.f;
#pragma unroll
        for (int j = 0; j < 32; j++) {
            const float w = wr[lane + 32 * j];
            a0 += xv0[j] * w;
            a1 += xv1[j] * w;
        }
#pragma unroll
        for (int off = 16; off; off >>= 1) {
            a0 += __shfl_xor_sync(0xffffffffu, a0, off);
            a1 += __shfl_xor_sync(0xffffffffu, a1, off);
        }
        lg[0][e] = a0; lg[1][e] = a1;
    }

    if (lane == 0) {
#pragma unroll
        for (int q = 0; q < 2; q++) {
            const int t = t0 + q;
            float mx = lg[q][0];
#pragma unroll
            for (int e = 1; e < EZ_EXP; e++) mx = fmaxf(mx, lg[q][e]);
            float sc[EZ_EXP], s = 0.f;
#pragma unroll
            for (int e = 0; e < EZ_EXP; e++) { sc[e] = __expf(lg[q][e] - mx); s += sc[e]; }
            const float inv = 1.f / s;
            float bsc[EZ_EXP];
#pragma unroll
            for (int e = 0; e < EZ_EXP; e++) { sc[e] *= inv; bsc[e] = sc[e] + bias[e]; }

            int i1 = 0;
#pragma unroll
            for (int e = 1; e < EZ_EXP; e++) if (bsc[e] > bsc[i1]) i1 = e;
            int i2 = (i1 == 0) ? 1 : 0;
#pragma unroll
            for (int e = 0; e < EZ_EXP; e++) if (e != i1 && bsc[e] > bsc[i2]) i2 = e;

            const float w1 = sc[i1], w2v = sc[i2];
            g_top_idx[2 * t] = i1;  g_top_idx[2 * t + 1] = i2;
            g_top_w[2 * t] = w1;    g_top_w[2 * t + 1] = w2v;
            float zs = 0.f;
            if (i1 >= E_EXP) zs += w1;
            if (i2 >= E_EXP) zs += w2v;
            g_zero_scale[t] = zs;

            if (i1 < E_EXP) atomicAdd(&g_blk[i1][chunk], 1);
            if (i2 < E_EXP) atomicAdd(&g_blk[i2][chunk], 1);
        }
    }
}

// ============================================================================
// single-sync stable scatter (proven)
// ============================================================================
__global__ void __launch_bounds__(256) scatter_kernel()
{
    const int e = blockIdx.x, j = blockIdx.y;
    const int tid = threadIdx.x, lane = tid & 31, w = tid >> 5;
    __shared__ int wtot[8];

    unsigned bal[4];
    int cnt = 0;
#pragma unroll
    for (int it = 0; it < 4; it++) {
        const int slot = j * 1024 + w * 128 + it * 32 + lane;
        const int f = (g_top_idx[slot] == e) ? 1 : 0;
        bal[it] = __ballot_sync(0xffffffffu, f);
        cnt += __popc(bal[it]);
    }
    if (lane == 0) wtot[w] = cnt;
    __syncthreads();

    int cbase = 0;
#pragma unroll
    for (int i = 0; i < 16; i++) {
        const int v = g_blk[e][i];
        if (i < j) cbase += v;
    }
    if (tid == 0 && j == 0) {
        int tot = 0;
#pragma unroll
        for (int i = 0; i < 16; i++) tot += g_blk[e][i];
        g_counts[e] = tot;
    }
    int run = cbase;
    for (int i = 0; i < w; i++) run += wtot[i];

#pragma unroll
    for (int it = 0; it < 4; it++) {
        const int slot = j * 1024 + w * 128 + it * 32 + lane;
        if ((bal[it] >> lane) & 1u) {
            const int pos = run + __popc(bal[it] & ((1u << lane) - 1u));
            g_rows[e * T_TOK + pos] = slot;
        }
        run += __popc(bal[it]);
    }
}

// ============================================================================
// HMMA GEMMs. CTA tile 128x128 but FOUR warps (2Mx2N), warp tile 64x64
// -> A ldsm amplification x2 (was x4). 128 threads, 2 CTAs/SM, 256-reg budget.
// K chunk 64 (4 kk), NSTG=2, ROWB=144 (conflict-free ldsm).
// Per-iter (race-free): WAIT0 -> sync -> issue c+1 into p^1 -> commit -> compute p.
// ============================================================================
#define ROWB   144
#define MATB   (128 * ROWB)          // 18432
#define STAGE  (2 * MATB)            // 36864
#define SMEM_DYN (2 * STAGE)         // 73728

// ---- up GEMM + SiLU: A = x(fp16), B = w13 interleaved gate/up. grid (E*64, 8)
__global__ void __launch_bounds__(128, 2) up_gemm_mma()
{
    const int e  = blockIdx.x >> 6;
    const int mt = blockIdx.x & 63;
    const int cnt = g_counts[e];
    const int m0 = mt * 128;
    if (m0 >= cnt) return;
    const int rcount = min(128, cnt - m0);
    const int ib = blockIdx.y * 64;

    extern __shared__ char sm[];
    const u32 smu = smem_u32(sm);
    __shared__ int s_slot[128];
    __shared__ int s_tok[128];

    const int tid = threadIdx.x, lane = tid & 31, wid = tid >> 5;
    const int wm = wid >> 1, wn = wid & 1;

    {
        const int sl0 = g_rows[e * T_TOK + m0 + min(tid, rcount - 1)];
        const int sl1 = g_rows[e * T_TOK + m0 + min(tid + 64, rcount - 1)];
        // 128 threads cover 128 rows in two halves? tid in [0,128): one row each
        s_slot[tid] = sl0;
        s_tok[tid] = sl0 >> 1;
        (void)sl1;
    }
    __syncthreads();

    // loads: per stage 2048 16B chunks (A 1024 + B 1024); 16 per thread.
    const int rr0 = tid >> 3, ch = tid & 7;   // rr0 in [0,16)
    const u32 dstA = (u32)(rr0 * ROWB + ch * 16);
    const u32 dstB = (u32)(MATB + rr0 * ROWB + ch * 16);
    const char* srcA[8];
#pragma unroll
    for (int t = 0; t < 8; t++)
        srcA[t] = (const char*)(g_xh + (size_t)s_tok[rr0 + 16 * t] * H_DIM + ch * 8);
    const int wrow0 = (rr0 & 1) ? (512 + ib + (rr0 >> 1)) : (ib + (rr0 >> 1));
    const char* srcB0 = (const char*)(g_w13h + ((size_t)e * 1024 + wrow0) * H_DIM + ch * 8);
    // row rr0+16t has same parity; wrow advances by 8 -> byte stride 8*H_DIM*2 = 16384

    float acc[4][8][4];
#pragma unroll
    for (int i = 0; i < 4; i++)
#pragma unroll
        for (int j = 0; j < 8; j++)
#pragma unroll
            for (int q = 0; q < 4; q++) acc[i][j][q] = 0.f;

    // prologue: stage 0 <- chunk 0
#pragma unroll
    for (int t = 0; t < 8; t++) {
        CPA16(smu + dstA + t * 16 * ROWB, srcA[t]);
        CPA16(smu + dstB + t * 16 * ROWB, srcB0 + t * 16384);
    }
    CPCOMMIT();

    const u32 lrow = (u32)(lane & 15) * ROWB + (u32)((lane >> 4) << 4);

#pragma unroll 1
    for (int c = 0; c < 16; c++) {
        const int p = c & 1;
        CPWAIT0();                 // chunk c complete (this thread)
        __syncthreads();           // stage p visible; all done computing c-1 => p^1 free
        if (c + 1 < 16) {
            const u32 sb = smu + (p ^ 1) * STAGE;
            const size_t go = (size_t)(c + 1) * 128;
#pragma unroll
            for (int t = 0; t < 8; t++) {
                CPA16(sb + dstA + t * 16 * ROWB, srcA[t] + go);
                CPA16(sb + dstB + t * 16 * ROWB, srcB0 + t * 16384 + go);
            }
        }
        CPCOMMIT();

        const u32 aB = smu + p * STAGE + (u32)(wm * 64) * ROWB + lrow;
        const u32 bB = smu + p * STAGE + MATB + (u32)(wn * 64) * ROWB + lrow;
#pragma unroll
        for (int kk = 0; kk < 4; kk++) {
            const u32 ko = kk * 32;
            u32 a[4][4], b[4][4];
#pragma unroll
            for (int mi = 0; mi < 4; mi++)
                ldsm4(a[mi][0], a[mi][1], a[mi][2], a[mi][3], aB + mi * 16 * ROWB + ko);
#pragma unroll
            for (int g = 0; g < 4; g++)
                ldsm4(b[g][0], b[g][1], b[g][2], b[g][3], bB + g * 16 * ROWB + ko);
#pragma unroll
            for (int mi = 0; mi < 4; mi++)
#pragma unroll
                for (int nj = 0; nj < 8; nj++) {
                    const int g = nj >> 1, o = nj & 1;
                    mma_f16(acc[mi][nj], a[mi], b[g][o], b[g][o + 2]);
                }
        }
    }

    // epilogue: (c0,c1)/(c2,c3) = (gate, up) for rows m, m+8
    const int qr = lane >> 2, qc = lane & 3;
#pragma unroll
    for (int mi = 0; mi < 4; mi++) {
        const int mlo = wm * 64 + mi * 16 + qr;
#pragma unroll
        for (int nj = 0; nj < 8; nj++) {
            const int icol = ib + wn * 32 + nj * 4 + qc;
            const float* a4 = acc[mi][nj];
            if (mlo < rcount) {
                const float g = a4[0], u = a4[1];
                g_acth[(size_t)s_slot[mlo] * I_DIM + icol] =
                    __float2half_rn(g / (1.f + __expf(-g)) * u);
            }
            if (mlo + 8 < rcount) {
                const float g = a4[2], u = a4[3];
                g_acth[(size_t)s_slot[mlo + 8] * I_DIM + icol] =
                    __float2half_rn(g / (1.f + __expf(-g)) * u);
            }
        }
    }
}

// ---- down GEMM: A = act(fp16), B = w2. K=512 (8 chunks of 64). grid (E*64, 8)
__global__ void __launch_bounds__(128, 2) down_gemm_mma()
{
    const int e  = blockIdx.x >> 6;
    const int mt = blockIdx.x & 63;
    const int cnt = g_counts[e];
    const int m0 = mt * 128;
    if (m0 >= cnt) return;
    const int rcount = min(128, cnt - m0);
    const int hb = blockIdx.y * 128;

    extern __shared__ char sm[];
    const u32 smu = smem_u32(sm);
    __shared__ int   s_slot[128];
    __shared__ float s_wt[128];

    const int tid = threadIdx.x, lane = tid & 31, wid = tid >> 5;
    const int wm = wid >> 1, wn = wid & 1;

    {
        const int sl = g_rows[e * T_TOK + m0 + min(tid, rcount - 1)];
        s_slot[tid] = sl;
        s_wt[tid] = g_top_w[sl] * SCALE_F;
    }
    __syncthreads();

    const int rr0 = tid >> 3, ch = tid & 7;
    const u32 dstA = (u32)(rr0 * ROWB + ch * 16);
    const u32 dstB = (u32)(MATB + rr0 * ROWB + ch * 16);
    const char* srcA[8];
#pragma unroll
    for (int t = 0; t < 8; t++)
        srcA[t] = (const char*)(g_acth + (size_t)s_slot[rr0 + 16 * t] * I_DIM + ch * 8);
    const char* srcB0 = (const char*)(g_w2h + ((size_t)e * H_DIM + hb + rr0) * I_DIM + ch * 8);
    // row stride 16 * I_DIM * 2 = 16384 bytes

    float acc[4][8][4];
#pragma unroll
    for (int i = 0; i < 4; i++)
#pragma unroll
        for (int j = 0; j < 8; j++)
#pragma unroll
            for (int q = 0; q < 4; q++) acc[i][j][q] = 0.f;

#pragma unroll
    for (int t = 0; t < 8; t++) {
        CPA16(smu + dstA + t * 16 * ROWB, srcA[t]);
        CPA16(smu + dstB + t * 16 * ROWB, srcB0 + t * 16384);
    }
    CPCOMMIT();

    const u32 lrow = (u32)(lane & 15) * ROWB + (u32)((lane >> 4) << 4);

#pragma unroll 1
    for (int c = 0; c < 8; c++) {
        const int p = c & 1;
        CPWAIT0();
        __syncthreads();
        if (c + 1 < 8) {
            const u32 sb = smu + (p ^ 1) * STAGE;
            const size_t go = (size_t)(c + 1) * 128;
#pragma unroll
            for (int t = 0; t < 8; t++) {
                CPA16(sb + dstA + t * 16 * ROWB, srcA[t] + go);
                CPA16(sb + dstB + t * 16 * ROWB, srcB0 + t * 16384 + go);
            }
        }
        CPCOMMIT();

        const u32 aB = smu + p * STAGE + (u32)(wm * 64) * ROWB + lrow;
        const u32 bB = smu + p * STAGE + MATB + (u32)(wn * 64) * ROWB + lrow;
#pragma unroll
        for (int kk = 0; kk < 4; kk++) {
            const u32 ko = kk * 32;
            u32 a[4][4], b[4][4];
#pragma unroll
            for (int mi = 0; mi < 4; mi++)
                ldsm4(a[mi][0], a[mi][1], a[mi][2], a[mi][3], aB + mi * 16 * ROWB + ko);
#pragma unroll
            for (int g = 0; g < 4; g++)
                ldsm4(b[g][0], b[g][1], b[g][2], b[g][3], bB + g * 16 * ROWB + ko);
#pragma unroll
            for (int mi = 0; mi < 4; mi++)
#pragma unroll
                for (int nj = 0; nj < 8; nj++) {
                    const int g = nj >> 1, o = nj & 1;
                    mma_f16(acc[mi][nj], a[mi], b[g][o], b[g][o + 2]);
                }
        }
    }

    const int qr = lane >> 2, qc = lane & 3;
#pragma unroll
    for (int mi = 0; mi < 4; mi++) {
        const int mlo = wm * 64 + mi * 16 + qr;
#pragma unroll
        for (int nj = 0; nj < 8; nj++) {
            const int n0 = hb + wn * 64 + nj * 8 + 2 * qc;
            const float* a4 = acc[mi][nj];
            if (mlo < rcount) {
                const float wt = s_wt[mlo];
                *(__half2*)(g_yh + (size_t)s_slot[mlo] * H_DIM + n0) =
                    __halves2half2(__float2half_rn(wt * a4[0]), __float2half_rn(wt * a4[1]));
            }
            if (mlo + 8 < rcount) {
                const float wt = s_wt[mlo + 8];
                *(__half2*)(g_yh + (size_t)s_slot[mlo + 8] * H_DIM + n0) =
                    __halves2half2(__float2half_rn(wt * a4[2]), __float2half_rn(wt * a4[3]));
            }
        }
    }
}

// ============================================================================
// finalize: out = zero_scale*x + slot sums (fp16 y)
// ============================================================================
__global__ void __launch_bounds__(256) finalize_kernel(
    const float* __restrict__ x, float* __restrict__ out)
{
    const int t = blockIdx.x;
    const float zs = g_zero_scale[t];
    const bool r0 = g_top_idx[2 * t]     < E_EXP;
    const bool r1 = g_top_idx[2 * t + 1] < E_EXP;
    const int h = threadIdx.x * 4;

    float4 xv = *(const float4*)(x + (size_t)t * H_DIM + h);
    float4 o;
    o.x = zs * xv.x; o.y = zs * xv.y; o.z = zs * xv.z; o.w = zs * xv.w;
    if (r0) {
        const __half2* y = (const __half2*)(g_yh + (size_t)(2 * t) * H_DIM + h);
        const float2 a = __half22float2(y[0]), b = __half22float2(y[1]);
        o.x += a.x; o.y += a.y; o.z += b.x; o.w += b.y;
    }
    if (r1) {
        const __half2* y = (const __half2*)(g_yh + (size_t)(2 * t + 1) * H_DIM + h);
        const float2 a = __half22float2(y[0]), b = __half22float2(y[1]);
        o.x += a.x; o.y += a.y; o.z += b.x; o.w += b.y;
    }
    *(float4*)(out + (size_t)t * H_DIM + h) = o;
}

// ============================================================================
// launch
// ============================================================================
extern "C" void kernel_launch(void* const* d_in, const int* in_sizes, int n_in,
                              void* d_out, int out_size)
{
    const float* x    = (const float*)d_in[0];
    const float* rw   = (const float*)d_in[1];
    const float* bias = (const float*)d_in[2];
    const float* w13  = (const float*)d_in[3];
    const float* w2   = (const float*)d_in[4];
    float* out = (float*)d_out;

    cudaFuncSetAttribute(up_gemm_mma,   cudaFuncAttributeMaxDynamicSharedMemorySize, SMEM_DYN);
    cudaFuncSetAttribute(down_gemm_mma, cudaFuncAttributeMaxDynamicSharedMemorySize, SMEM_DYN);

    cvt_w_kernel<<<(int)((W13_ELEMS + (size_t)E_EXP * H_DIM * I_DIM) / 1024), 256>>>(w13, w2);
    router_kernel<<<T_TOK / 16, 256>>>(x, rw, bias);

    dim3 gl(E_EXP, 16);
    scatter_kernel<<<gl, 256>>>();

    dim3 gu(E_EXP * 64, 8);
    up_gemm_mma<<<gu, 128, SMEM_DYN>>>();

    dim3 gd(E_EXP * 64, 8);
    down_gemm_mma<<<gd, 128, SMEM_DYN>>>();

    finalize_kernel<<<T_TOK, 256>>>(x, out);
}

// round 15
// speedup vs baseline: 1.4566x; 1.4566x over previous
#include <cuda_runtime.h>
#include <cuda_fp16.h>
#include <cstdint>

#define T_TOK   8192
#define H_DIM   1024
#define I_DIM   512
#define E_EXP   8
#define EZ_EXP  12
#define SCALE_F 2.5f

typedef unsigned int u32;
typedef unsigned long long u64;

// ---------------- scratch (device globals; no allocation) ----------------
__device__ int    g_top_idx[T_TOK * 2];
__device__ float  g_top_w[T_TOK * 2];
__device__ float  g_zero_scale[T_TOK];
__device__ int    g_counts[E_EXP];
__device__ int    g_blk[E_EXP][16];          // zero-init at load; re-zeroed by finalize
__device__ int    g_rows[E_EXP * T_TOK];
__device__ __half g_xh[(size_t)T_TOK * H_DIM];
__device__ __half g_w13h[(size_t)E_EXP * 2 * I_DIM * H_DIM];
__device__ __half g_w2h[(size_t)E_EXP * H_DIM * I_DIM];
__device__ __half g_acth[(size_t)T_TOK * 2 * I_DIM];
__device__ __half g_yh[(size_t)T_TOK * 2 * H_DIM];

// ---------------- helpers ----------------
__device__ __forceinline__ u32 smem_u32(const void* p) {
    u32 a;
    asm("{ .reg .u64 t; cvta.to.shared.u64 t, %1; cvt.u32.u64 %0, t; }" : "=r"(a) : "l"(p));
    return a;
}

#define CPA16(dst, src) \
    asm volatile("{.reg .u64 g; cvta.to.global.u64 g, %1; cp.async.cg.shared.global [%0], [g], 16;}\n" \
                 :: "r"((u32)(dst)), "l"(src) : "memory")
#define CPCOMMIT() asm volatile("cp.async.commit_group;" ::: "memory")
#define CPWAIT0()  asm volatile("cp.async.wait_group 0;" ::: "memory")

__device__ __forceinline__ void ldsm4(u32& r0, u32& r1, u32& r2, u32& r3, u32 addr) {
    asm volatile("ldmatrix.sync.aligned.m8n8.x4.shared.b16 {%0,%1,%2,%3}, [%4];"
                 : "=r"(r0), "=r"(r1), "=r"(r2), "=r"(r3) : "r"(addr));
}

__device__ __forceinline__ void mma_f16(float* d, const u32* a, u32 b0, u32 b1) {
    asm volatile("mma.sync.aligned.m16n8k16.row.col.f32.f16.f16.f32 "
        "{%0,%1,%2,%3}, {%4,%5,%6,%7}, {%8,%9}, {%0,%1,%2,%3};"
        : "+f"(d[0]), "+f"(d[1]), "+f"(d[2]), "+f"(d[3])
        : "r"(a[0]), "r"(a[1]), "r"(a[2]), "r"(a[3]), "r"(b0), "r"(b1));
}

// ============================================================================
// fused router + weight-conversion kernel.
// Blocks [0, 512): router (48KB smem). Blocks [512, 512+CV_BLOCKS): w13/w2->fp16.
// CV_BLOCKS = (W13_ELEMS + W2_ELEMS) / 4 / 256 = 12582912/1024 = 12288.
// g_blk pre-zeroed (static init on first run; finalize re-zeros thereafter).
// ============================================================================
#define W13_ELEMS ((size_t)E_EXP * 2 * I_DIM * H_DIM)    // 8388608
#define W2_ELEMS  ((size_t)E_EXP * H_DIM * I_DIM)        // 4194304
#define RT_BLOCKS 512
#define CV_BLOCKS 12288                                   // (W13+W2)/4/256

__global__ void __launch_bounds__(256) router_cvt_kernel(
    const float* __restrict__ x, const float* __restrict__ rw, const float* __restrict__ bias,
    const float* __restrict__ w13, const float* __restrict__ w2)
{
    const int tid = threadIdx.x;

    if (blockIdx.x >= RT_BLOCKS) {
        // ---- conversion part ----
        const size_t gid = (size_t)(blockIdx.x - RT_BLOCKS) * 256 + tid;
        const float* src; __half* dst; size_t off;
        if (gid < W13_ELEMS / 4) { src = w13; dst = g_w13h; off = gid * 4; }
        else { src = w2; dst = g_w2h; off = (gid - W13_ELEMS / 4) * 4; }
        const float4 v = *(const float4*)(src + off);
        *(__half2*)(dst + off)     = __halves2half2(__float2half_rn(v.x), __float2half_rn(v.y));
        *(__half2*)(dst + off + 2) = __halves2half2(__float2half_rn(v.z), __float2half_rn(v.w));
        return;
    }

    // ---- router part (proven; 2 tokens/warp, fused x->fp16, fused counting) ----
    __shared__ float srw[EZ_EXP * H_DIM];
    for (int i = tid; i < EZ_EXP * H_DIM; i += 256) srw[i] = rw[i];
    __syncthreads();

    const int warp = tid >> 5, lane = tid & 31;
    const int t0 = blockIdx.x * 16 + warp * 2;
    const int chunk = blockIdx.x >> 5;
    const float* xr0 = x + (size_t)t0 * H_DIM;
    const float* xr1 = x + (size_t)(t0 + 1) * H_DIM;

    float xv0[32], xv1[32];
#pragma unroll
    for (int j = 0; j < 32; j++) { xv0[j] = xr0[lane + 32 * j]; xv1[j] = xr1[lane + 32 * j]; }

    __half* xh0 = g_xh + (size_t)t0 * H_DIM;
    __half* xh1 = g_xh + (size_t)(t0 + 1) * H_DIM;
#pragma unroll
    for (int j = 0; j < 32; j++) {
        xh0[lane + 32 * j] = __float2half_rn(xv0[j]);
        xh1[lane + 32 * j] = __float2half_rn(xv1[j]);
    }

    float lg[2][EZ_EXP];
#pragma unroll
    for (int e = 0; e < EZ_EXP; e++) {
        const float* wr = srw + e * H_DIM;
        float a0 = 0.f, a1 = 0.f;
#pragma unroll
        for (int j = 0; j < 32; j++) {
            const float w = wr[lane + 32 * j];
            a0 += xv0[j] * w;
            a1 += xv1[j] * w;
        }
#pragma unroll
        for (int off = 16; off; off >>= 1) {
            a0 += __shfl_xor_sync(0xffffffffu, a0, off);
            a1 += __shfl_xor_sync(0xffffffffu, a1, off);
        }
        lg[0][e] = a0; lg[1][e] = a1;
    }

    if (lane == 0) {
#pragma unroll
        for (int q = 0; q < 2; q++) {
            const int t = t0 + q;
            float mx = lg[q][0];
#pragma unroll
            for (int e = 1; e < EZ_EXP; e++) mx = fmaxf(mx, lg[q][e]);
            float sc[EZ_EXP], s = 0.f;
#pragma unroll
            for (int e = 0; e < EZ_EXP; e++) { sc[e] = __expf(lg[q][e] - mx); s += sc[e]; }
            const float inv = 1.f / s;
            float bsc[EZ_EXP];
#pragma unroll
            for (int e = 0; e < EZ_EXP; e++) { sc[e] *= inv; bsc[e] = sc[e] + bias[e]; }

            int i1 = 0;
#pragma unroll
            for (int e = 1; e < EZ_EXP; e++) if (bsc[e] > bsc[i1]) i1 = e;
            int i2 = (i1 == 0) ? 1 : 0;
#pragma unroll
            for (int e = 0; e < EZ_EXP; e++) if (e != i1 && bsc[e] > bsc[i2]) i2 = e;

            const float w1 = sc[i1], w2v = sc[i2];
            g_top_idx[2 * t] = i1;  g_top_idx[2 * t + 1] = i2;
            g_top_w[2 * t] = w1;    g_top_w[2 * t + 1] = w2v;
            float zs = 0.f;
            if (i1 >= E_EXP) zs += w1;
            if (i2 >= E_EXP) zs += w2v;
            g_zero_scale[t] = zs;

            if (i1 < E_EXP) atomicAdd(&g_blk[i1][chunk], 1);
            if (i2 < E_EXP) atomicAdd(&g_blk[i2][chunk], 1);
        }
    }
}

// ============================================================================
// single-sync stable scatter (proven)
// ============================================================================
__global__ void __launch_bounds__(256) scatter_kernel()
{
    const int e = blockIdx.x, j = blockIdx.y;
    const int tid = threadIdx.x, lane = tid & 31, w = tid >> 5;
    __shared__ int wtot[8];

    unsigned bal[4];
    int cnt = 0;
#pragma unroll
    for (int it = 0; it < 4; it++) {
        const int slot = j * 1024 + w * 128 + it * 32 + lane;
        const int f = (g_top_idx[slot] == e) ? 1 : 0;
        bal[it] = __ballot_sync(0xffffffffu, f);
        cnt += __popc(bal[it]);
    }
    if (lane == 0) wtot[w] = cnt;
    __syncthreads();

    int cbase = 0;
#pragma unroll
    for (int i = 0; i < 16; i++) {
        const int v = g_blk[e][i];
        if (i < j) cbase += v;
    }
    if (tid == 0 && j == 0) {
        int tot = 0;
#pragma unroll
        for (int i = 0; i < 16; i++) tot += g_blk[e][i];
        g_counts[e] = tot;
    }
    int run = cbase;
    for (int i = 0; i < w; i++) run += wtot[i];

#pragma unroll
    for (int it = 0; it < 4; it++) {
        const int slot = j * 1024 + w * 128 + it * 32 + lane;
        if ((bal[it] >> lane) & 1u) {
            const int pos = run + __popc(bal[it] & ((1u << lane) - 1u));
            g_rows[e * T_TOK + pos] = slot;
        }
        run += __popc(bal[it]);
    }
}

// ============================================================================
// HMMA GEMMs — R12 champion, byte-identical.
// CTA 128x128, 8 warps (2Mx4N), warp tile 64x32, K chunk 64 (4 kk), NSTG=2,
// ROWB=144. Per-iter: WAIT0 -> sync -> issue c+1 into p^1 -> commit -> compute p.
// ============================================================================
#define ROWB   144
#define MATB   (128 * ROWB)          // 18432
#define STAGE  (2 * MATB)            // 36864
#define SMEM_DYN (2 * STAGE)         // 73728

// ---- up GEMM + SiLU: A = x(fp16), B = w13 interleaved gate/up. grid (E*64, 8)
__global__ void __launch_bounds__(256, 2) up_gemm_mma()
{
    const int e  = blockIdx.x >> 6;
    const int mt = blockIdx.x & 63;
    const int cnt = g_counts[e];
    const int m0 = mt * 128;
    if (m0 >= cnt) return;
    const int rcount = min(128, cnt - m0);
    const int ib = blockIdx.y * 64;

    extern __shared__ char sm[];
    const u32 smu = smem_u32(sm);
    __shared__ int s_slot[128];
    __shared__ int s_tok[128];

    const int tid = threadIdx.x, lane = tid & 31, wid = tid >> 5;
    const int wm = wid >> 2, wn = wid & 3;

    if (tid < 128) {
        const int sl = g_rows[e * T_TOK + m0 + min(tid, rcount - 1)];
        s_slot[tid] = sl;
        s_tok[tid] = sl >> 1;
    }
    __syncthreads();

    const int rr0 = tid >> 3, ch = tid & 7;
    const u32 dstA = (u32)(rr0 * ROWB + ch * 16);
    const u32 dstB = (u32)(MATB + rr0 * ROWB + ch * 16);
    const char* srcA[4];
    const char* srcB[4];
#pragma unroll
    for (int t = 0; t < 4; t++) {
        const int rr = rr0 + 32 * t;
        srcA[t] = (const char*)(g_xh + (size_t)s_tok[rr] * H_DIM + ch * 8);
        const int wrow = (rr & 1) ? (512 + ib + (rr >> 1)) : (ib + (rr >> 1));
        srcB[t] = (const char*)(g_w13h + ((size_t)e * 1024 + wrow) * H_DIM + ch * 8);
    }

    float acc[4][4][4];
#pragma unroll
    for (int i = 0; i < 4; i++)
#pragma unroll
        for (int j = 0; j < 4; j++)
#pragma unroll
            for (int q = 0; q < 4; q++) acc[i][j][q] = 0.f;

#pragma unroll
    for (int t = 0; t < 4; t++) {
        CPA16(smu + dstA + t * 32 * ROWB, srcA[t]);
        CPA16(smu + dstB + t * 32 * ROWB, srcB[t]);
    }
    CPCOMMIT();

    const u32 lrow = (u32)(lane & 15) * ROWB + (u32)((lane >> 4) << 4);

#pragma unroll 1
    for (int c = 0; c < 16; c++) {
        const int p = c & 1;
        CPWAIT0();
        __syncthreads();
        if (c + 1 < 16) {
            const u32 sb = smu + (p ^ 1) * STAGE;
            const size_t go = (size_t)(c + 1) * 128;
#pragma unroll
            for (int t = 0; t < 4; t++) {
                CPA16(sb + dstA + t * 32 * ROWB, srcA[t] + go);
                CPA16(sb + dstB + t * 32 * ROWB, srcB[t] + go);
            }
        }
        CPCOMMIT();

        const u32 aB = smu + p * STAGE + (u32)(wm * 64) * ROWB + lrow;
        const u32 bB = smu + p * STAGE + MATB + (u32)(wn * 32) * ROWB + lrow;
#pragma unroll
        for (int kk = 0; kk < 4; kk++) {
            const u32 ko = kk * 32;
            u32 a[4][4], b[2][4];
#pragma unroll
            for (int mi = 0; mi < 4; mi++)
                ldsm4(a[mi][0], a[mi][1], a[mi][2], a[mi][3], aB + mi * 16 * ROWB + ko);
            ldsm4(b[0][0], b[0][1], b[0][2], b[0][3], bB + ko);
            ldsm4(b[1][0], b[1][1], b[1][2], b[1][3], bB + 16 * ROWB + ko);
#pragma unroll
            for (int mi = 0; mi < 4; mi++)
#pragma unroll
                for (int nj = 0; nj < 4; nj++) {
                    const int g = nj >> 1, o = nj & 1;
                    mma_f16(acc[mi][nj], a[mi], b[g][o], b[g][o + 2]);
                }
        }
    }

    const int qr = lane >> 2, qc = lane & 3;
#pragma unroll
    for (int mi = 0; mi < 4; mi++) {
        const int mlo = wm * 64 + mi * 16 + qr;
#pragma unroll
        for (int nj = 0; nj < 4; nj++) {
            const int icol = ib + wn * 16 + nj * 4 + qc;
            const float* a4 = acc[mi][nj];
            if (mlo < rcount) {
                const float g = a4[0], u = a4[1];
                g_acth[(size_t)s_slot[mlo] * I_DIM + icol] =
                    __float2half_rn(g / (1.f + __expf(-g)) * u);
            }
            if (mlo + 8 < rcount) {
                const float g = a4[2], u = a4[3];
                g_acth[(size_t)s_slot[mlo + 8] * I_DIM + icol] =
                    __float2half_rn(g / (1.f + __expf(-g)) * u);
            }
        }
    }
}

// ---- down GEMM: A = act(fp16), B = w2. K=512 (8 chunks of 64). grid (E*64, 8)
__global__ void __launch_bounds__(256, 2) down_gemm_mma()
{
    const int e  = blockIdx.x >> 6;
    const int mt = blockIdx.x & 63;
    const int cnt = g_counts[e];
    const int m0 = mt * 128;
    if (m0 >= cnt) return;
    const int rcount = min(128, cnt - m0);
    const int hb = blockIdx.y * 128;

    extern __shared__ char sm[];
    const u32 smu = smem_u32(sm);
    __shared__ int   s_slot[128];
    __shared__ float s_wt[128];

    const int tid = threadIdx.x, lane = tid & 31, wid = tid >> 5;
    const int wm = wid >> 2, wn = wid & 3;

    if (tid < 128) {
        const int sl = g_rows[e * T_TOK + m0 + min(tid, rcount - 1)];
        s_slot[tid] = sl;
        s_wt[tid] = g_top_w[sl] * SCALE_F;
    }
    __syncthreads();

    const int rr0 = tid >> 3, ch = tid & 7;
    const u32 dstA = (u32)(rr0 * ROWB + ch * 16);
    const u32 dstB = (u32)(MATB + rr0 * ROWB + ch * 16);
    const char* srcA[4];
    const char* srcB[4];
#pragma unroll
    for (int t = 0; t < 4; t++) {
        const int rr = rr0 + 32 * t;
        srcA[t] = (const char*)(g_acth + (size_t)s_slot[rr] * I_DIM + ch * 8);
        srcB[t] = (const char*)(g_w2h + ((size_t)e * H_DIM + hb + rr) * I_DIM + ch * 8);
    }

    float acc[4][4][4];
#pragma unroll
    for (int i = 0; i < 4; i++)
#pragma unroll
        for (int j = 0; j < 4; j++)
#pragma unroll
            for (int q = 0; q < 4; q++) acc[i][j][q] = 0.f;

#pragma unroll
    for (int t = 0; t < 4; t++) {
        CPA16(smu + dstA + t * 32 * ROWB, srcA[t]);
        CPA16(smu + dstB + t * 32 * ROWB, srcB[t]);
    }
    CPCOMMIT();

    const u32 lrow = (u32)(lane & 15) * ROWB + (u32)((lane >> 4) << 4);

#pragma unroll 1
    for (int c = 0; c < 8; c++) {
        const int p = c & 1;
        CPWAIT0();
        __syncthreads();
        if (c + 1 < 8) {
            const u32 sb = smu + (p ^ 1) * STAGE;
            const size_t go = (size_t)(c + 1) * 128;
#pragma unroll
            for (int t = 0; t < 4; t++) {
                CPA16(sb + dstA + t * 32 * ROWB, srcA[t] + go);
                CPA16(sb + dstB + t * 32 * ROWB, srcB[t] + go);
            }
        }
        CPCOMMIT();

        const u32 aB = smu + p * STAGE + (u32)(wm * 64) * ROWB + lrow;
        const u32 bB = smu + p * STAGE + MATB + (u32)(wn * 32) * ROWB + lrow;
#pragma unroll
        for (int kk = 0; kk < 4; kk++) {
            const u32 ko = kk * 32;
            u32 a[4][4], b[2][4];
#pragma unroll
            for (int mi = 0; mi < 4; mi++)
                ldsm4(a[mi][0], a[mi][1], a[mi][2], a[mi][3], aB + mi * 16 * ROWB + ko);
            ldsm4(b[0][0], b[0][1], b[0][2], b[0][3], bB + ko);
            ldsm4(b[1][0], b[1][1], b[1][2], b[1][3], bB + 16 * ROWB + ko);
#pragma unroll
            for (int mi = 0; mi < 4; mi++)
#pragma unroll
                for (int nj = 0; nj < 4; nj++) {
                    const int g = nj >> 1, o = nj & 1;
                    mma_f16(acc[mi][nj], a[mi], b[g][o], b[g][o + 2]);
                }
        }
    }

    const int qr = lane >> 2, qc = lane & 3;
#pragma unroll
    for (int mi = 0; mi < 4; mi++) {
        const int mlo = wm * 64 + mi * 16 + qr;
#pragma unroll
        for (int nj = 0; nj < 4; nj++) {
            const int n0 = hb + wn * 32 + nj * 8 + 2 * qc;
            const float* a4 = acc[mi][nj];
            if (mlo < rcount) {
                const float wt = s_wt[mlo];
                *(__half2*)(g_yh + (size_t)s_slot[mlo] * H_DIM + n0) =
                    __halves2half2(__float2half_rn(wt * a4[0]), __float2half_rn(wt * a4[1]));
            }
            if (mlo + 8 < rcount) {
                const float wt = s_wt[mlo + 8];
                *(__half2*)(g_yh + (size_t)s_slot[mlo + 8] * H_DIM + n0) =
                    __halves2half2(__float2half_rn(wt * a4[2]), __float2half_rn(wt * a4[3]));
            }
        }
    }
}

// ============================================================================
// finalize: out = zero_scale*x + slot sums (fp16 y); re-zero g_blk for the
// next kernel_launch execution (runs strictly after scatter's reads).
// ============================================================================
__global__ void __launch_bounds__(256) finalize_kernel(
    const float* __restrict__ x, float* __restrict__ out)
{
    if (blockIdx.x == 0 && threadIdx.x < E_EXP * 16)
        ((int*)g_blk)[threadIdx.x] = 0;

    const int t = blockIdx.x;
    const float zs = g_zero_scale[t];
    const bool r0 = g_top_idx[2 * t]     < E_EXP;
    const bool r1 = g_top_idx[2 * t + 1] < E_EXP;
    const int h = threadIdx.x * 4;

    float4 xv = *(const float4*)(x + (size_t)t * H_DIM + h);
    float4 o;
    o.x = zs * xv.x; o.y = zs * xv.y; o.z = zs * xv.z; o.w = zs * xv.w;
    if (r0) {
        const __half2* y = (const __half2*)(g_yh + (size_t)(2 * t) * H_DIM + h);
        const float2 a = __half22float2(y[0]), b = __half22float2(y[1]);
        o.x += a.x; o.y += a.y; o.z += b.x; o.w += b.y;
    }
    if (r1) {
        const __half2* y = (const __half2*)(g_yh + (size_t)(2 * t + 1) * H_DIM + h);
        const float2 a = __half22float2(y[0]), b = __half22float2(y[1]);
        o.x += a.x; o.y += a.y; o.z += b.x; o.w += b.y;
    }
    *(float4*)(out + (size_t)t * H_DIM + h) = o;
}

// ============================================================================
// launch
// ============================================================================
extern "C" void kernel_launch(void* const* d_in, const int* in_sizes, int n_in,
                              void* d_out, int out_size)
{
    const float* x    = (const float*)d_in[0];
    const float* rw   = (const float*)d_in[1];
    const float* bias = (const float*)d_in[2];
    const float* w13  = (const float*)d_in[3];
    const float* w2   = (const float*)d_in[4];
    float* out = (float*)d_out;

    cudaFuncSetAttribute(up_gemm_mma,   cudaFuncAttributeMaxDynamicSharedMemorySize, SMEM_DYN);
    cudaFuncSetAttribute(down_gemm_mma, cudaFuncAttributeMaxDynamicSharedMemorySize, SMEM_DYN);

    router_cvt_kernel<<<RT_BLOCKS + CV_BLOCKS, 256>>>(x, rw, bias, w13, w2);

    dim3 gl(E_EXP, 16);
    scatter_kernel<<<gl, 256>>>();

    dim3 gu(E_EXP * 64, 8);
    up_gemm_mma<<<gu, 256, SMEM_DYN>>>();

    dim3 gd(E_EXP * 64, 8);
    down_gemm_mma<<<gd, 256, SMEM_DYN>>>();

    finalize_kernel<<<T_TOK, 256>>>(x, out);
}

// round 16
// speedup vs baseline: 1.5297x; 1.0501x over previous
#include <cuda_runtime.h>
#include <cuda_fp16.h>
#include <cstdint>

#define T_TOK   8192
#define H_DIM   1024
#define I_DIM   512
#define E_EXP   8
#define EZ_EXP  12
#define SCALE_F 2.5f

typedef unsigned int u32;
typedef unsigned long long u64;

// ---------------- scratch (device globals; no allocation) ----------------
__device__ int    g_top_idx[T_TOK * 2];
__device__ float  g_top_w[T_TOK * 2];
__device__ float  g_zero_scale[T_TOK];
__device__ int    g_counts[E_EXP];
__device__ int    g_blk[E_EXP][16];
__device__ int    g_rows[E_EXP * T_TOK];
__device__ __half g_xh[(size_t)T_TOK * H_DIM];
__device__ __half g_w13h[(size_t)E_EXP * 2 * I_DIM * H_DIM];
__device__ __half g_w2h[(size_t)E_EXP * H_DIM * I_DIM];
__device__ __half g_acth[(size_t)T_TOK * 2 * I_DIM];
__device__ __half g_yh[(size_t)T_TOK * 2 * H_DIM];

// ---------------- helpers ----------------
__device__ __forceinline__ u32 smem_u32(const void* p) {
    u32 a;
    asm("{ .reg .u64 t; cvta.to.shared.u64 t, %1; cvt.u32.u64 %0, t; }" : "=r"(a) : "l"(p));
    return a;
}

#define CPA16(dst, src) \
    asm volatile("{.reg .u64 g; cvta.to.global.u64 g, %1; cp.async.cg.shared.global [%0], [g], 16;}\n" \
                 :: "r"((u32)(dst)), "l"(src) : "memory")
#define CPCOMMIT() asm volatile("cp.async.commit_group;" ::: "memory")
#define CPWAIT0()  asm volatile("cp.async.wait_group 0;" ::: "memory")

__device__ __forceinline__ void ldsm4(u32& r0, u32& r1, u32& r2, u32& r3, u32 addr) {
    asm volatile("ldmatrix.sync.aligned.m8n8.x4.shared.b16 {%0,%1,%2,%3}, [%4];"
                 : "=r"(r0), "=r"(r1), "=r"(r2), "=r"(r3) : "r"(addr));
}

__device__ __forceinline__ void mma_f16(float* d, const u32* a, u32 b0, u32 b1) {
    asm volatile("mma.sync.aligned.m16n8k16.row.col.f32.f16.f16.f32 "
        "{%0,%1,%2,%3}, {%4,%5,%6,%7}, {%8,%9}, {%0,%1,%2,%3};"
        : "+f"(d[0]), "+f"(d[1]), "+f"(d[2]), "+f"(d[3])
        : "r"(a[0]), "r"(a[1]), "r"(a[2]), "r"(a[3]), "r"(b0), "r"(b1));
}

// ============================================================================
// weight conversion (one-time) + zero g_blk for the router's atomic counting
// ============================================================================
#define W13_ELEMS ((size_t)E_EXP * 2 * I_DIM * H_DIM)
__global__ void __launch_bounds__(256) cvt_w_kernel(
    const float* __restrict__ w13, const float* __restrict__ w2)
{
    if (blockIdx.x == 0 && threadIdx.x < E_EXP * 16)
        ((int*)g_blk)[threadIdx.x] = 0;

    const size_t gid = (size_t)blockIdx.x * 256 + threadIdx.x;
    const float* src; __half* dst; size_t off;
    if (gid < W13_ELEMS / 4) { src = w13; dst = g_w13h; off = gid * 4; }
    else { src = w2; dst = g_w2h; off = (gid - W13_ELEMS / 4) * 4; }
    const float4 v = *(const float4*)(src + off);
    *(__half2*)(dst + off)     = __halves2half2(__float2half_rn(v.x), __float2half_rn(v.y));
    *(__half2*)(dst + off + 2) = __halves2half2(__float2half_rn(v.z), __float2half_rn(v.w));
}

// ============================================================================
// router + fused x->fp16 conversion + fused per-chunk expert counting (proven)
// ============================================================================
__global__ void __launch_bounds__(256) router_kernel(
    const float* __restrict__ x, const float* __restrict__ rw, const float* __restrict__ bias)
{
    __shared__ float srw[EZ_EXP * H_DIM];
    const int tid = threadIdx.x;
    for (int i = tid; i < EZ_EXP * H_DIM; i += 256) srw[i] = rw[i];
    __syncthreads();

    const int warp = tid >> 5, lane = tid & 31;
    const int t0 = blockIdx.x * 16 + warp * 2;
    const int chunk = blockIdx.x >> 5;
    const float* xr0 = x + (size_t)t0 * H_DIM;
    const float* xr1 = x + (size_t)(t0 + 1) * H_DIM;

    float xv0[32], xv1[32];
#pragma unroll
    for (int j = 0; j < 32; j++) { xv0[j] = xr0[lane + 32 * j]; xv1[j] = xr1[lane + 32 * j]; }

    __half* xh0 = g_xh + (size_t)t0 * H_DIM;
    __half* xh1 = g_xh + (size_t)(t0 + 1) * H_DIM;
#pragma unroll
    for (int j = 0; j < 32; j++) {
        xh0[lane + 32 * j] = __float2half_rn(xv0[j]);
        xh1[lane + 32 * j] = __float2half_rn(xv1[j]);
    }

    float lg[2][EZ_EXP];
#pragma unroll
    for (int e = 0; e < EZ_EXP; e++) {
        const float* wr = srw + e * H_DIM;
        float a0 = 0.f, a1 = 0.f;
#pragma unroll
        for (int j = 0; j < 32; j++) {
            const float w = wr[lane + 32 * j];
            a0 += xv0[j] * w;
            a1 += xv1[j] * w;
        }
#pragma unroll
        for (int off = 16; off; off >>= 1) {
            a0 += __shfl_xor_sync(0xffffffffu, a0, off);
            a1 += __shfl_xor_sync(0xffffffffu, a1, off);
        }
        lg[0][e] = a0; lg[1][e] = a1;
    }

    if (lane == 0) {
#pragma unroll
        for (int q = 0; q < 2; q++) {
            const int t = t0 + q;
            float mx = lg[q][0];
#pragma unroll
            for (int e = 1; e < EZ_EXP; e++) mx = fmaxf(mx, lg[q][e]);
            float sc[EZ_EXP], s = 0.f;
#pragma unroll
            for (int e = 0; e < EZ_EXP; e++) { sc[e] = __expf(lg[q][e] - mx); s += sc[e]; }
            const float inv = 1.f / s;
            float bsc[EZ_EXP];
#pragma unroll
            for (int e = 0; e < EZ_EXP; e++) { sc[e] *= inv; bsc[e] = sc[e] + bias[e]; }

            int i1 = 0;
#pragma unroll
            for (int e = 1; e < EZ_EXP; e++) if (bsc[e] > bsc[i1]) i1 = e;
            int i2 = (i1 == 0) ? 1 : 0;
#pragma unroll
            for (int e = 0; e < EZ_EXP; e++) if (e != i1 && bsc[e] > bsc[i2]) i2 = e;

            const float w1 = sc[i1], w2v = sc[i2];
            g_top_idx[2 * t] = i1;  g_top_idx[2 * t + 1] = i2;
            g_top_w[2 * t] = w1;    g_top_w[2 * t + 1] = w2v;
            float zs = 0.f;
            if (i1 >= E_EXP) zs += w1;
            if (i2 >= E_EXP) zs += w2v;
            g_zero_scale[t] = zs;

            if (i1 < E_EXP) atomicAdd(&g_blk[i1][chunk], 1);
            if (i2 < E_EXP) atomicAdd(&g_blk[i2][chunk], 1);
        }
    }
}

// ============================================================================
// single-sync stable scatter (proven)
// ============================================================================
__global__ void __launch_bounds__(256) scatter_kernel()
{
    const int e = blockIdx.x, j = blockIdx.y;
    const int tid = threadIdx.x, lane = tid & 31, w = tid >> 5;
    __shared__ int wtot[8];

    unsigned bal[4];
    int cnt = 0;
#pragma unroll
    for (int it = 0; it < 4; it++) {
        const int slot = j * 1024 + w * 128 + it * 32 + lane;
        const int f = (g_top_idx[slot] == e) ? 1 : 0;
        bal[it] = __ballot_sync(0xffffffffu, f);
        cnt += __popc(bal[it]);
    }
    if (lane == 0) wtot[w] = cnt;
    __syncthreads();

    int cbase = 0;
#pragma unroll
    for (int i = 0; i < 16; i++) {
        const int v = g_blk[e][i];
        if (i < j) cbase += v;
    }
    if (tid == 0 && j == 0) {
        int tot = 0;
#pragma unroll
        for (int i = 0; i < 16; i++) tot += g_blk[e][i];
        g_counts[e] = tot;
    }
    int run = cbase;
    for (int i = 0; i < w; i++) run += wtot[i];

#pragma unroll
    for (int it = 0; it < 4; it++) {
        const int slot = j * 1024 + w * 128 + it * 32 + lane;
        if ((bal[it] >> lane) & 1u) {
            const int pos = run + __popc(bal[it] & ((1u << lane) - 1u));
            g_rows[e * T_TOK + pos] = slot;
        }
        run += __popc(bal[it]);
    }
}

// ============================================================================
// HMMA GEMMs — R12 champion, byte-identical.
// CTA 128x128, 8 warps (2Mx4N), warp tile 64x32, K chunk 64 (4 kk), NSTG=2,
// ROWB=144. Per-iter: WAIT0 -> sync -> issue c+1 into p^1 -> commit -> compute p.
// ============================================================================
#define ROWB   144
#define MATB   (128 * ROWB)          // 18432
#define STAGE  (2 * MATB)            // 36864
#define SMEM_DYN (2 * STAGE)         // 73728

// ---- up GEMM + SiLU: A = x(fp16), B = w13 interleaved gate/up. grid (E*64, 8)
__global__ void __launch_bounds__(256, 2) up_gemm_mma()
{
    const int e  = blockIdx.x >> 6;
    const int mt = blockIdx.x & 63;
    const int cnt = g_counts[e];
    const int m0 = mt * 128;
    if (m0 >= cnt) return;
    const int rcount = min(128, cnt - m0);
    const int ib = blockIdx.y * 64;

    extern __shared__ char sm[];
    const u32 smu = smem_u32(sm);
    __shared__ int s_slot[128];
    __shared__ int s_tok[128];

    const int tid = threadIdx.x, lane = tid & 31, wid = tid >> 5;
    const int wm = wid >> 2, wn = wid & 3;

    if (tid < 128) {
        const int sl = g_rows[e * T_TOK + m0 + min(tid, rcount - 1)];
        s_slot[tid] = sl;
        s_tok[tid] = sl >> 1;
    }
    __syncthreads();

    const int rr0 = tid >> 3, ch = tid & 7;
    const u32 dstA = (u32)(rr0 * ROWB + ch * 16);
    const u32 dstB = (u32)(MATB + rr0 * ROWB + ch * 16);
    const char* srcA[4];
    const char* srcB[4];
#pragma unroll
    for (int t = 0; t < 4; t++) {
        const int rr = rr0 + 32 * t;
        srcA[t] = (const char*)(g_xh + (size_t)s_tok[rr] * H_DIM + ch * 8);
        const int wrow = (rr & 1) ? (512 + ib + (rr >> 1)) : (ib + (rr >> 1));
        srcB[t] = (const char*)(g_w13h + ((size_t)e * 1024 + wrow) * H_DIM + ch * 8);
    }

    float acc[4][4][4];
#pragma unroll
    for (int i = 0; i < 4; i++)
#pragma unroll
        for (int j = 0; j < 4; j++)
#pragma unroll
            for (int q = 0; q < 4; q++) acc[i][j][q] = 0.f;

#pragma unroll
    for (int t = 0; t < 4; t++) {
        CPA16(smu + dstA + t * 32 * ROWB, srcA[t]);
        CPA16(smu + dstB + t * 32 * ROWB, srcB[t]);
    }
    CPCOMMIT();

    const u32 lrow = (u32)(lane & 15) * ROWB + (u32)((lane >> 4) << 4);

#pragma unroll 1
    for (int c = 0; c < 16; c++) {
        const int p = c & 1;
        CPWAIT0();
        __syncthreads();
        if (c + 1 < 16) {
            const u32 sb = smu + (p ^ 1) * STAGE;
            const size_t go = (size_t)(c + 1) * 128;
#pragma unroll
            for (int t = 0; t < 4; t++) {
                CPA16(sb + dstA + t * 32 * ROWB, srcA[t] + go);
                CPA16(sb + dstB + t * 32 * ROWB, srcB[t] + go);
            }
        }
        CPCOMMIT();

        const u32 aB = smu + p * STAGE + (u32)(wm * 64) * ROWB + lrow;
        const u32 bB = smu + p * STAGE + MATB + (u32)(wn * 32) * ROWB + lrow;
#pragma unroll
        for (int kk = 0; kk < 4; kk++) {
            const u32 ko = kk * 32;
            u32 a[4][4], b[2][4];
#pragma unroll
            for (int mi = 0; mi < 4; mi++)
                ldsm4(a[mi][0], a[mi][1], a[mi][2], a[mi][3], aB + mi * 16 * ROWB + ko);
            ldsm4(b[0][0], b[0][1], b[0][2], b[0][3], bB + ko);
            ldsm4(b[1][0], b[1][1], b[1][2], b[1][3], bB + 16 * ROWB + ko);
#pragma unroll
            for (int mi = 0; mi < 4; mi++)
#pragma unroll
                for (int nj = 0; nj < 4; nj++) {
                    const int g = nj >> 1, o = nj & 1;
                    mma_f16(acc[mi][nj], a[mi], b[g][o], b[g][o + 2]);
                }
        }
    }

    const int qr = lane >> 2, qc = lane & 3;
#pragma unroll
    for (int mi = 0; mi < 4; mi++) {
        const int mlo = wm * 64 + mi * 16 + qr;
#pragma unroll
        for (int nj = 0; nj < 4; nj++) {
            const int icol = ib + wn * 16 + nj * 4 + qc;
            const float* a4 = acc[mi][nj];
            if (mlo < rcount) {
                const float g = a4[0], u = a4[1];
                g_acth[(size_t)s_slot[mlo] * I_DIM + icol] =
                    __float2half_rn(g / (1.f + __expf(-g)) * u);
            }
            if (mlo + 8 < rcount) {
                const float g = a4[2], u = a4[3];
                g_acth[(size_t)s_slot[mlo + 8] * I_DIM + icol] =
                    __float2half_rn(g / (1.f + __expf(-g)) * u);
            }
        }
    }
}

// ---- down GEMM: A = act(fp16), B = w2. K=512 (8 chunks of 64). grid (E*64, 8)
__global__ void __launch_bounds__(256, 2) down_gemm_mma()
{
    const int e  = blockIdx.x >> 6;
    const int mt = blockIdx.x & 63;
    const int cnt = g_counts[e];
    const int m0 = mt * 128;
    if (m0 >= cnt) return;
    const int rcount = min(128, cnt - m0);
    const int hb = blockIdx.y * 128;

    extern __shared__ char sm[];
    const u32 smu = smem_u32(sm);
    __shared__ int   s_slot[128];
    __shared__ float s_wt[128];

    const int tid = threadIdx.x, lane = tid & 31, wid = tid >> 5;
    const int wm = wid >> 2, wn = wid & 3;

    if (tid < 128) {
        const int sl = g_rows[e * T_TOK + m0 + min(tid, rcount - 1)];
        s_slot[tid] = sl;
        s_wt[tid] = g_top_w[sl] * SCALE_F;
    }
    __syncthreads();

    const int rr0 = tid >> 3, ch = tid & 7;
    const u32 dstA = (u32)(rr0 * ROWB + ch * 16);
    const u32 dstB = (u32)(MATB + rr0 * ROWB + ch * 16);
    const char* srcA[4];
    const char* srcB[4];
#pragma unroll
    for (int t = 0; t < 4; t++) {
        const int rr = rr0 + 32 * t;
        srcA[t] = (const char*)(g_acth + (size_t)s_slot[rr] * I_DIM + ch * 8);
        srcB[t] = (const char*)(g_w2h + ((size_t)e * H_DIM + hb + rr) * I_DIM + ch * 8);
    }

    float acc[4][4][4];
#pragma unroll
    for (int i = 0; i < 4; i++)
#pragma unroll
        for (int j = 0; j < 4; j++)
#pragma unroll
            for (int q = 0; q < 4; q++) acc[i][j][q] = 0.f;

#pragma unroll
    for (int t = 0; t < 4; t++) {
        CPA16(smu + dstA + t * 32 * ROWB, srcA[t]);
        CPA16(smu + dstB + t * 32 * ROWB, srcB[t]);
    }
    CPCOMMIT();

    const u32 lrow = (u32)(lane & 15) * ROWB + (u32)((lane >> 4) << 4);

#pragma unroll 1
    for (int c = 0; c < 8; c++) {
        const int p = c & 1;
        CPWAIT0();
        __syncthreads();
        if (c + 1 < 8) {
            const u32 sb = smu + (p ^ 1) * STAGE;
            const size_t go = (size_t)(c + 1) * 128;
#pragma unroll
            for (int t = 0; t < 4; t++) {
                CPA16(sb + dstA + t * 32 * ROWB, srcA[t] + go);
                CPA16(sb + dstB + t * 32 * ROWB, srcB[t] + go);
            }
        }
        CPCOMMIT();

        const u32 aB = smu + p * STAGE + (u32)(wm * 64) * ROWB + lrow;
        const u32 bB = smu + p * STAGE + MATB + (u32)(wn * 32) * ROWB + lrow;
#pragma unroll
        for (int kk = 0; kk < 4; kk++) {
            const u32 ko = kk * 32;
            u32 a[4][4], b[2][4];
#pragma unroll
            for (int mi = 0; mi < 4; mi++)
                ldsm4(a[mi][0], a[mi][1], a[mi][2], a[mi][3], aB + mi * 16 * ROWB + ko);
            ldsm4(b[0][0], b[0][1], b[0][2], b[0][3], bB + ko);
            ldsm4(b[1][0], b[1][1], b[1][2], b[1][3], bB + 16 * ROWB + ko);
#pragma unroll
            for (int mi = 0; mi < 4; mi++)
#pragma unroll
                for (int nj = 0; nj < 4; nj++) {
                    const int g = nj >> 1, o = nj & 1;
                    mma_f16(acc[mi][nj], a[mi], b[g][o], b[g][o + 2]);
                }
        }
    }

    const int qr = lane >> 2, qc = lane & 3;
#pragma unroll
    for (int mi = 0; mi < 4; mi++) {
        const int mlo = wm * 64 + mi * 16 + qr;
#pragma unroll
        for (int nj = 0; nj < 4; nj++) {
            const int n0 = hb + wn * 32 + nj * 8 + 2 * qc;
            const float* a4 = acc[mi][nj];
            if (mlo < rcount) {
                const float wt = s_wt[mlo];
                *(__half2*)(g_yh + (size_t)s_slot[mlo] * H_DIM + n0) =
                    __halves2half2(__float2half_rn(wt * a4[0]), __float2half_rn(wt * a4[1]));
            }
            if (mlo + 8 < rcount) {
                const float wt = s_wt[mlo + 8];
                *(__half2*)(g_yh + (size_t)s_slot[mlo + 8] * H_DIM + n0) =
                    __halves2half2(__float2half_rn(wt * a4[2]), __float2half_rn(wt * a4[3]));
            }
        }
    }
}

// ============================================================================
// finalize: out = zero_scale*x + slot sums (fp16 y)
// ============================================================================
__global__ void __launch_bounds__(256) finalize_kernel(
    const float* __restrict__ x, float* __restrict__ out)
{
    const int t = blockIdx.x;
    const float zs = g_zero_scale[t];
    const bool r0 = g_top_idx[2 * t]     < E_EXP;
    const bool r1 = g_top_idx[2 * t + 1] < E_EXP;
    const int h = threadIdx.x * 4;

    float4 xv = *(const float4*)(x + (size_t)t * H_DIM + h);
    float4 o;
    o.x = zs * xv.x; o.y = zs * xv.y; o.z = zs * xv.z; o.w = zs * xv.w;
    if (r0) {
        const __half2* y = (const __half2*)(g_yh + (size_t)(2 * t) * H_DIM + h);
        const float2 a = __half22float2(y[0]), b = __half22float2(y[1]);
        o.x += a.x; o.y += a.y; o.z += b.x; o.w += b.y;
    }
    if (r1) {
        const __half2* y = (const __half2*)(g_yh + (size_t)(2 * t + 1) * H_DIM + h);
        const float2 a = __half22float2(y[0]), b = __half22float2(y[1]);
        o.x += a.x; o.y += a.y; o.z += b.x; o.w += b.y;
    }
    *(float4*)(out + (size_t)t * H_DIM + h) = o;
}

// ============================================================================
// launch
// ============================================================================
extern "C" void kernel_launch(void* const* d_in, const int* in_sizes, int n_in,
                              void* d_out, int out_size)
{
    const float* x    = (const float*)d_in[0];
    const float* rw   = (const float*)d_in[1];
    const float* bias = (const float*)d_in[2];
    const float* w13  = (const float*)d_in[3];
    const float* w2   = (const float*)d_in[4];
    float* out = (float*)d_out;

    cudaFuncSetAttribute(up_gemm_mma,   cudaFuncAttributeMaxDynamicSharedMemorySize, SMEM_DYN);
    cudaFuncSetAttribute(down_gemm_mma, cudaFuncAttributeMaxDynamicSharedMemorySize, SMEM_DYN);

    cvt_w_kernel<<<(int)((W13_ELEMS + (size_t)E_EXP * H_DIM * I_DIM) / 1024), 256>>>(w13, w2);
    router_kernel<<<T_TOK / 16, 256>>>(x, rw, bias);

    dim3 gl(E_EXP, 16);
    scatter_kernel<<<gl, 256>>>();

    dim3 gu(E_EXP * 64, 8);
    up_gemm_mma<<<gu, 256, SMEM_DYN>>>();

    dim3 gd(E_EXP * 64, 8);
    down_gemm_mma<<<gd, 256, SMEM_DYN>>>();

    finalize_kernel<<<T_TOK, 256>>>(x, out);
}